// round 14
// baseline (speedup 1.0000x reference)
#include <cuda_runtime.h>
#include <cuda_bf16.h>
#include <cuda_fp16.h>
#include <math.h>
#include <stdint.h>

#define NB 256   // batch
#define NL 128   // seq len
#define NC 256   // input channels
#define NH 512   // hidden
#define NG 2048  // 4*H

__device__ __forceinline__ uint32_t smem_u32_of(const void* p) {
    uint32_t a;
    asm("{ .reg .u64 t; cvta.to.shared.u64 t, %1; cvt.u32.u64 %0, t; }" : "=r"(a) : "l"(p));
    return a;
}

// ===================== device globals (no allocation allowed) ===============
__device__ float g_bvp[NG];                           // folded bias, permuted cols
__device__ __half g_WhmT_cat[(size_t)NG * 1536];      // [n' perm][1536] = [hi|lo|hi] of Whm^T
__device__ __half g_Wmh_cat[(size_t)NH * 1536];       // [k'][1536] = [hi|hi|lo] of Wmh
__device__ __half g_Wmx_cat[(size_t)NC * 1536];       // [c][1536]  = [hi|hi|lo] of Wmx
__device__ __half g_Wp16[(size_t)NG * NH];            // fp16(W'^T) permuted [n'][512]
__device__ __half g_Wb16[(size_t)NG * NC];            // fp16(Wbig^T) perm [n'][256]
__device__ __half g_x16[(size_t)NB * NL * NC];        // fp16(x) [m][256]
__device__ __half g_h16[2][(size_t)NB * NH];          // hidden fp16, ping-pong
__device__ __half g_P16[(size_t)NL * NB * NG];        // TIME-MAJOR fp16: [t][b][n']
__device__ float g_alpha[NB * NC];                    // softmax weights (time-invariant)
__device__ int   g_bar[4 * 32];                       // barrier counters, 128B apart
// cell state lives in registers inside the persistent scan kernel

// ===================== prep kernels =========================================
__global__ void init_state_kernel() {
    int i = blockIdx.x * blockDim.x + threadIdx.x;
    if (i < NB * NH) g_h16[0][i] = __float2half_rn(0.f);
    if (i < NG) g_bvp[i] = 0.f;
    if (i < 4 * 32) g_bar[i] = 0;
}

__device__ __forceinline__ int perm_col(int n) {       // natural gate col -> permuted
    int j = n & 511, g = n >> 9;
    return ((j >> 3) << 5) | (g << 3) | (j & 7);
}

// split-K bvec: grid (8 n-blocks, 8 k-slices), atomicAdd into zeroed g_bvp
__global__ void bvec_kernel(const float* __restrict__ bih, const float* __restrict__ bhm,
                            const float* __restrict__ bmx, const float* __restrict__ bmh,
                            const float* __restrict__ Whm) {
    int n = blockIdx.x * blockDim.x + threadIdx.x;
    int k0 = blockIdx.y * 64;
    float acc[8] = {};
    for (int kk = 0; kk < 64; kk += 8) {
#pragma unroll
        for (int u = 0; u < 8; u++) {
            int k = k0 + kk + u;
            acc[u] = fmaf(bmx[k] + bmh[k], Whm[(size_t)k * NG + n], acc[u]);
        }
    }
    float s = (blockIdx.y == 0) ? (bih[n] + bhm[n]) : 0.f;
#pragma unroll
    for (int u = 0; u < 8; u++) s += acc[u];
    atomicAdd(&g_bvp[perm_col(n)], s);
}

// elementwise hi/lo split + K-concat: src fp32 [R][512] -> dst fp16 [R][1536]=[hi|hi|lo]
__global__ void splitcat_kernel(const float* __restrict__ src, __half* __restrict__ dst) {
    int i = blockIdx.x * blockDim.x + threadIdx.x;     // float4 index over R*512/4
    float4 v = reinterpret_cast<const float4*>(src)[i];
    float f[4] = {v.x, v.y, v.z, v.w};
    union { __half h[4]; uint2 u; } H, L;
#pragma unroll
    for (int k = 0; k < 4; k++) {
        H.h[k] = __float2half_rn(f[k]);
        L.h[k] = __float2half_rn(f[k] - __half2float(H.h[k]));
    }
    int r = (i * 4) >> 9, m = (i * 4) & 511;
    size_t base = (size_t)r * 1536 + m;
    *reinterpret_cast<uint2*>(dst + base)        = H.u;
    *reinterpret_cast<uint2*>(dst + base + 512)  = H.u;
    *reinterpret_cast<uint2*>(dst + base + 1024) = L.u;
}

// transpose + permute + split: Whm fp32 [512][2048] -> WhmT_cat [2048 perm][1536]=[hi|lo|hi]
__global__ void tsplitT_kernel(const float* __restrict__ src) {
    __shared__ float sA[32][33];
    const int n0 = blockIdx.x * 32, k0 = blockIdx.y * 32;
    const int t = threadIdx.x;
    {
        int nl = t & 31, rr = t >> 5;
#pragma unroll
        for (int it = 0; it < 4; it++) {
            int kl = it * 8 + rr;
            sA[kl][nl] = src[(size_t)(k0 + kl) * NG + n0 + nl];
        }
    }
    __syncthreads();
    int nlo = t >> 3, ks = t & 7;
    int np = perm_col(n0 + nlo);
    union { __half h[4]; uint2 u; } H, L;
#pragma unroll
    for (int kk = 0; kk < 4; kk++) {
        float v = sA[ks * 4 + kk][nlo];
        H.h[kk] = __float2half_rn(v);
        L.h[kk] = __float2half_rn(v - __half2float(H.h[kk]));
    }
    size_t base = (size_t)np * 1536 + k0 + ks * 4;
    *reinterpret_cast<uint2*>(g_WhmT_cat + base)        = H.u;
    *reinterpret_cast<uint2*>(g_WhmT_cat + base + 512)  = L.u;
    *reinterpret_cast<uint2*>(g_WhmT_cat + base + 1024) = H.u;
}

// x fp32 -> fp16 (elementwise)
__global__ void xsplit_kernel(const float* __restrict__ x) {
    size_t i = (size_t)blockIdx.x * blockDim.x + threadIdx.x;  // float4 index
    float4 v = reinterpret_cast<const float4*>(x)[i];
    union { __half h[4]; uint2 u; } H;
    H.h[0] = __float2half_rn(v.x); H.h[1] = __float2half_rn(v.y);
    H.h[2] = __float2half_rn(v.z); H.h[3] = __float2half_rn(v.w);
    reinterpret_cast<uint2*>(g_x16)[i] = H.u;
}

// ===================== shared HMMA GEMM =====================================
// C[M][N] = A[M][Kc] @ Bw[N][Kc]^T  (both K-major fp16).
// EPI=0: += g_bvp, store fp16 to g_P16 (time-major swizzle).
// EPI=1: store fp16 to Wout[r][col], ld=512.
// EPI=2: += Wih[col][inv_perm(r)], store fp16 to Wout[r][col], ld=256.
template <int EPI>
__global__ __launch_bounds__(256)
void gemm_mma(const __half* __restrict__ A, const __half* __restrict__ Bw, int Kc,
              __half* __restrict__ Wout, const float* __restrict__ Wih) {
    constexpr int BM = 128, BN = 128, WN_ = 4, MF = 4;
    __shared__ __half sA[2][BM][40];
    __shared__ __half sB[2][BN][40];
    const int tid = threadIdx.x, lane = tid & 31, w = tid >> 5;
    const int wn0 = (w % WN_) * 32, wm0 = (w / WN_) * 64;
    const int m0 = blockIdx.y * BM, n0 = blockIdx.x * BN;

    auto load_stage = [&](int s, int k0) {
#pragma unroll
        for (int i = 0; i < (BM + BN) * 4 / 256; i++) {
            int q = i * 256 + tid;
            const __half* src;
            uint32_t dst;
            if (q < BM * 4) {
                int r = q >> 2, c = q & 3;
                src = A + (size_t)(m0 + r) * Kc + k0 + c * 8;
                dst = smem_u32_of(&sA[s][r][c * 8]);
            } else {
                int q2 = q - BM * 4, r = q2 >> 2, c = q2 & 3;
                src = Bw + (size_t)(n0 + r) * Kc + k0 + c * 8;
                dst = smem_u32_of(&sB[s][r][c * 8]);
            }
            asm volatile("cp.async.cg.shared.global [%0], [%1], 16;" :: "r"(dst), "l"(src));
        }
        asm volatile("cp.async.commit_group;");
    };

    float acc[MF][4][4] = {};
    const int arow = (lane & 7) + ((lane >> 3) & 1) * 8;
    const int akm  = (lane >> 4) & 1;
    const int brow = lane & 7;
    const int bkm  = (lane >> 3) & 1;

    const int NIT = Kc >> 5;
    load_stage(0, 0);
    for (int it = 0; it < NIT; it++) {
        if (it + 1 < NIT) {
            load_stage((it + 1) & 1, (it + 1) * 32);
            asm volatile("cp.async.wait_group 1;");
        } else {
            asm volatile("cp.async.wait_group 0;");
        }
        __syncthreads();
        int s = it & 1;
#pragma unroll
        for (int ks = 0; ks < 2; ks++) {
            uint32_t aR[MF][4], bR[4][2];
#pragma unroll
            for (int ni = 0; ni < 4; ni++) {
                uint32_t ad = smem_u32_of(&sB[s][wn0 + ni * 8 + brow][ks * 16 + bkm * 8]);
                asm volatile("ldmatrix.sync.aligned.m8n8.x2.shared.b16 {%0,%1}, [%2];"
                             : "=r"(bR[ni][0]), "=r"(bR[ni][1]) : "r"(ad));
            }
#pragma unroll
            for (int mi = 0; mi < MF; mi++) {
                uint32_t ad = smem_u32_of(&sA[s][wm0 + mi * 16 + arow][ks * 16 + akm * 8]);
                asm volatile("ldmatrix.sync.aligned.m8n8.x4.shared.b16 {%0,%1,%2,%3}, [%4];"
                             : "=r"(aR[mi][0]), "=r"(aR[mi][1]), "=r"(aR[mi][2]), "=r"(aR[mi][3])
                             : "r"(ad));
            }
#pragma unroll
            for (int mi = 0; mi < MF; mi++)
#pragma unroll
                for (int ni = 0; ni < 4; ni++)
                    asm volatile(
                        "mma.sync.aligned.m16n8k16.row.col.f32.f16.f16.f32 "
                        "{%0,%1,%2,%3}, {%4,%5,%6,%7}, {%8,%9}, {%0,%1,%2,%3};"
                        : "+f"(acc[mi][ni][0]), "+f"(acc[mi][ni][1]),
                          "+f"(acc[mi][ni][2]), "+f"(acc[mi][ni][3])
                        : "r"(aR[mi][0]), "r"(aR[mi][1]), "r"(aR[mi][2]), "r"(aR[mi][3]),
                          "r"(bR[ni][0]), "r"(bR[ni][1]));
        }
        __syncthreads();
    }

    constexpr int Nld = (EPI == 1) ? NH : NC;
#pragma unroll
    for (int mi = 0; mi < MF; mi++) {
#pragma unroll
        for (int half = 0; half < 2; half++) {
            int r = m0 + wm0 + mi * 16 + (lane >> 2) + half * 8;
            if (EPI == 0) {
                size_t dr = (size_t)(r & (NL - 1)) * NB + (size_t)(r >> 7);
#pragma unroll
                for (int ni = 0; ni < 4; ni++) {
                    int col = n0 + wn0 + ni * 8 + (lane & 3) * 2;
                    *reinterpret_cast<__half2*>(&g_P16[dr * NG + col]) =
                        __floats2half2_rn(acc[mi][ni][half * 2 + 0] + g_bvp[col],
                                          acc[mi][ni][half * 2 + 1] + g_bvp[col + 1]);
                }
            } else {
                int n_nat = 0;
                if (EPI == 2) {
                    int low3 = r & 7, g = (r >> 3) & 3, jj = ((r >> 5) << 3) | low3;
                    n_nat = (g << 9) | jj;
                }
#pragma unroll
                for (int ni = 0; ni < 4; ni++) {
                    int col = n0 + wn0 + ni * 8 + (lane & 3) * 2;
                    float v0 = acc[mi][ni][half * 2 + 0];
                    float v1 = acc[mi][ni][half * 2 + 1];
                    if (EPI == 2) {
                        v0 += Wih[(size_t)col * NG + n_nat];
                        v1 += Wih[(size_t)(col + 1) * NG + n_nat];
                    }
                    *reinterpret_cast<__half2*>(Wout + (size_t)r * Nld + col) =
                        __halves2half2(__float2half_rn(v0), __float2half_rn(v1));
                }
            }
        }
    }
}

// ===================== x_tilde: alpha + scale ================================
__global__ void alpha_kernel(const float* __restrict__ x, const float* __restrict__ Wa,
                             const float* __restrict__ ba) {
    __shared__ float red[NC];
    __shared__ float s_wa[NL];
    int b = blockIdx.x, c = threadIdx.x;
    if (c < NL) s_wa[c] = Wa[2 * NH + c];
    __syncthreads();
    const float* xb = x + (size_t)b * NL * NC;
    float s = ba[0];
#pragma unroll 16
    for (int l = 0; l < NL; l++) s = fmaf(xb[(size_t)l * NC + c], s_wa[l], s);
    red[c] = s; __syncthreads();
    for (int o = NC / 2; o > 0; o >>= 1) { if (c < o) red[c] = fmaxf(red[c], red[c + o]); __syncthreads(); }
    float mx = red[0]; __syncthreads();
    float e = expf(s - mx);
    red[c] = e; __syncthreads();
    for (int o = NC / 2; o > 0; o >>= 1) { if (c < o) red[c] += red[c + o]; __syncthreads(); }
    g_alpha[b * NC + c] = e / red[0];
}

__global__ void scale_kernel(const float* __restrict__ x, float* __restrict__ out) {
    size_t i = (size_t)blockIdx.x * blockDim.x + threadIdx.x;  // float4 index
    float4 v = reinterpret_cast<const float4*>(x)[i];
    int b = (int)(i >> 13);                    // / (NL*NC/4)
    int c4 = (int)(i & 63) << 2;
    float4 a = *reinterpret_cast<const float4*>(g_alpha + b * NC + c4);
    v.x *= a.x; v.y *= a.y; v.z *= a.z; v.w *= a.w;
    reinterpret_cast<float4*>(out)[i] = v;
}

// ===================== persistent scan kernel ===============================
// compute -> h-write -> loadP(t+1) -> fence(h only) -> barrier -> deferred out
static constexpr int SBP = 520;                        // halves (1040 B pitch)
static constexpr int SAP = 136;                        // halves (272 B pitch)
static constexpr int SA_STAGE = 64 * SAP;
static constexpr int SCAN_SMEM = (64 * SBP + 4 * SA_STAGE) * 2;   // 136,192 B

__device__ __forceinline__ void wait_grp(int n) {
    switch (n) {
        case 0: asm volatile("cp.async.wait_group 0;" ::: "memory"); break;
        case 1: asm volatile("cp.async.wait_group 1;" ::: "memory"); break;
        case 2: asm volatile("cp.async.wait_group 2;" ::: "memory"); break;
        default: asm volatile("cp.async.wait_group 3;" ::: "memory"); break;
    }
}

__global__ __launch_bounds__(256)
void scan_kernel(float* __restrict__ out) {
    extern __shared__ __half sm16[];
    __half* sB = sm16;                                // [64][520]
    __half* sA = sm16 + 64 * SBP;                     // [4][64][136]
    const int tid = threadIdx.x, lane = tid & 31, w = tid >> 5;
    const int n0 = blockIdx.x * 64, m0 = blockIdx.y * 64, grp = blockIdx.y;
    const int wn0 = (w & 1) * 32, wm0 = (w >> 1) * 16;

    // ---- resident B tile: W1 rows n0..n0+63, 512 cols ----------------------
#pragma unroll
    for (int i = 0; i < 16; i++) {
        int q = i * 256 + tid;
        int r = q >> 6, cc = q & 63;
        asm volatile("cp.async.cg.shared.global [%0], [%1], 16;"
                     :: "r"(smem_u32_of(sB + r * SBP + cc * 8)),
                        "l"(g_Wp16 + (size_t)(n0 + r) * NH + cc * 8));
    }
    asm volatile("cp.async.commit_group;");
    asm volatile("cp.async.wait_group 0;");
    __syncthreads();

    const int arow = (lane & 7) + ((lane >> 3) & 1) * 8;
    const int akm  = (lane >> 4) & 1;
    const int browB = ((lane >> 4) & 1) * 8 + (lane & 7);
    const int bkmB  = (lane >> 3) & 1;
    const int p0 = (lane & 3) * 2;
    const int j = ((n0 + wn0) >> 5) * 8 + p0;         // hidden unit (even)

    float creg[2][2] = {};                            // cell state in registers
    uint32_t pv[2][4];                                // prefetched P (half2 bits)
    float hnv[2][2], cnv[2][2];                       // deferred outputs

    auto loadP = [&](int tt) {
        const __half* Pt = g_P16 + (size_t)tt * NB * NG;
#pragma unroll
        for (int half = 0; half < 2; half++) {
            int b = m0 + wm0 + (lane >> 2) + half * 8;
#pragma unroll
            for (int ni = 0; ni < 4; ni++)
                pv[half][ni] = __ldg(reinterpret_cast<const uint32_t*>(
                    Pt + (size_t)b * NG + n0 + wn0 + ni * 8 + p0));
        }
    };
    auto storeOut = [&](int tt) {
#pragma unroll
        for (int half = 0; half < 2; half++) {
            int b = m0 + wm0 + (lane >> 2) + half * 8;
            size_t o = (size_t)b * (NL * NH) + (size_t)tt * NH + j;
            *reinterpret_cast<float2*>(&out[o]) = make_float2(hnv[half][0], hnv[half][1]);
            *reinterpret_cast<float2*>(&out[o + (size_t)NB * NL * NH]) =
                make_float2(cnv[half][0], cnv[half][1]);
        }
    };
    loadP(0);

    for (int t = 0; t < NL; t++) {
        const int par = t & 1;
        const __half* hsrc = g_h16[par];

        // issue ALL 4 A chunks (16 KB each) immediately
#pragma unroll
        for (int c = 0; c < 4; c++) {
#pragma unroll
            for (int i = 0; i < 4; i++) {
                int q = i * 256 + tid;
                int r = q >> 4, cc = q & 15;
                asm volatile("cp.async.cg.shared.global [%0], [%1], 16;"
                             :: "r"(smem_u32_of(sA + c * SA_STAGE + r * SAP + cc * 8)),
                                "l"(hsrc + (size_t)(m0 + r) * NH + c * 128 + cc * 8));
            }
            asm volatile("cp.async.commit_group;");
        }

        // deferred output stores for previous step (overlap with A-chunk latency)
        if (t > 0) storeOut(t - 1);

        float acc[4][4] = {};
#pragma unroll
        for (int c = 0; c < 4; c++) {
            wait_grp(3 - c);
            __syncthreads();
            const __half* As = sA + c * SA_STAGE;
            const int kb = c * 128;
#pragma unroll
            for (int ks = 0; ks < 8; ks++) {
                uint32_t aR[4];
                asm volatile("ldmatrix.sync.aligned.m8n8.x4.shared.b16 {%0,%1,%2,%3}, [%4];"
                             : "=r"(aR[0]), "=r"(aR[1]), "=r"(aR[2]), "=r"(aR[3])
                             : "r"(smem_u32_of(As + (wm0 + arow) * SAP + ks * 16 + akm * 8)));
#pragma unroll
                for (int p = 0; p < 2; p++) {
                    uint32_t b4[4];
                    asm volatile("ldmatrix.sync.aligned.m8n8.x4.shared.b16 {%0,%1,%2,%3}, [%4];"
                                 : "=r"(b4[0]), "=r"(b4[1]), "=r"(b4[2]), "=r"(b4[3])
                                 : "r"(smem_u32_of(sB + (wn0 + p * 16 + browB) * SBP
                                                   + kb + ks * 16 + bkmB * 8)));
                    asm volatile(
                        "mma.sync.aligned.m16n8k16.row.col.f32.f16.f16.f32 "
                        "{%0,%1,%2,%3}, {%4,%5,%6,%7}, {%8,%9}, {%0,%1,%2,%3};"
                        : "+f"(acc[2 * p][0]), "+f"(acc[2 * p][1]),
                          "+f"(acc[2 * p][2]), "+f"(acc[2 * p][3])
                        : "r"(aR[0]), "r"(aR[1]), "r"(aR[2]), "r"(aR[3]),
                          "r"(b4[0]), "r"(b4[1]));
                    asm volatile(
                        "mma.sync.aligned.m16n8k16.row.col.f32.f16.f16.f32 "
                        "{%0,%1,%2,%3}, {%4,%5,%6,%7}, {%8,%9}, {%0,%1,%2,%3};"
                        : "+f"(acc[2 * p + 1][0]), "+f"(acc[2 * p + 1][1]),
                          "+f"(acc[2 * p + 1][2]), "+f"(acc[2 * p + 1][3])
                        : "r"(aR[0]), "r"(aR[1]), "r"(aR[2]), "r"(aR[3]),
                          "r"(b4[2]), "r"(b4[3]));
                }
            }
        }

        // ---- fused LSTM pointwise epilogue: ONLY the h-write before fence --
        __half* hdst = g_h16[par ^ 1];
#pragma unroll
        for (int half = 0; half < 2; half++) {
            int b = m0 + wm0 + (lane >> 2) + half * 8;
#pragma unroll
            for (int e = 0; e < 2; e++) {
                int a = half * 2 + e;
                float2 pf0 = __half22float2(*reinterpret_cast<__half2*>(&pv[half][0]));
                float2 pf1 = __half22float2(*reinterpret_cast<__half2*>(&pv[half][1]));
                float2 pf2 = __half22float2(*reinterpret_cast<__half2*>(&pv[half][2]));
                float2 pf3 = __half22float2(*reinterpret_cast<__half2*>(&pv[half][3]));
                float iv = acc[0][a] + (e ? pf0.y : pf0.x);
                float fv = acc[1][a] + (e ? pf1.y : pf1.x);
                float gv = acc[2][a] + (e ? pf2.y : pf2.x);
                float ov = acc[3][a] + (e ? pf3.y : pf3.x);
                float si = 1.f / (1.f + expf(-iv));
                float sf = 1.f / (1.f + expf(-fv));
                float so = 1.f / (1.f + expf(-ov));
                float tg = tanhf(gv);
                float Cn = sf * creg[half][e] + si * tg;
                creg[half][e] = Cn;
                cnv[half][e] = Cn;
                hnv[half][e] = so * tanhf(Cn);
            }
            *reinterpret_cast<__half2*>(hdst + (size_t)b * NH + j) =
                __halves2half2(__float2half_rn(hnv[half][0]), __float2half_rn(hnv[half][1]));
        }

        // prefetch P for next step — overlaps fence + barrier wait
        if (t + 1 < NL) loadP(t + 1);

        // ---- per-m-group barrier (padded counters) ------------------------
        __threadfence();
        __syncthreads();
        if (tid == 0) {
            atomicAdd(&g_bar[grp * 32], 1);
            int target = 32 * (t + 1);
            while (*((volatile int*)&g_bar[grp * 32]) < target) __nanosleep(32);
        }
        __syncthreads();
    }
    storeOut(NL - 1);
}

// ===================== host =================================================
extern "C" void kernel_launch(void* const* d_in, const int* in_sizes, int n_in,
                              void* d_out, int out_size) {
    const float* x   = (const float*)d_in[0];
    const float* Wih = (const float*)d_in[1];
    const float* bih = (const float*)d_in[2];
    const float* Wmx = (const float*)d_in[3];
    const float* bmx = (const float*)d_in[4];
    const float* Wmh = (const float*)d_in[5];
    const float* bmh = (const float*)d_in[6];
    const float* Whm = (const float*)d_in[7];
    const float* bhm = (const float*)d_in[8];
    const float* Wa  = (const float*)d_in[9];
    const float* ba  = (const float*)d_in[10];
    float* out = (float*)d_out;

    __half *pWhmT, *pWmhC, *pWmxC, *pWp16, *pWb16, *pX16;
    cudaGetSymbolAddress((void**)&pWhmT, g_WhmT_cat);
    cudaGetSymbolAddress((void**)&pWmhC, g_Wmh_cat);
    cudaGetSymbolAddress((void**)&pWmxC, g_Wmx_cat);
    cudaGetSymbolAddress((void**)&pWp16, g_Wp16);
    cudaGetSymbolAddress((void**)&pWb16, g_Wb16);
    cudaGetSymbolAddress((void**)&pX16,  g_x16);

    cudaFuncSetAttribute(scan_kernel, cudaFuncAttributeMaxDynamicSharedMemorySize, SCAN_SMEM);

    init_state_kernel<<<(NB * NH + 255) / 256, 256>>>();
    bvec_kernel<<<dim3(8, 8), 256>>>(bih, bhm, bmx, bmh, Whm);

    // operand prep for HMMA weight folding
    splitcat_kernel<<<(NH * NH / 4) / 256, 256>>>(Wmh, pWmhC);     // [512][1536]
    splitcat_kernel<<<(NC * NH / 4) / 256, 256>>>(Wmx, pWmxC);     // [256][1536]
    tsplitT_kernel<<<dim3(NG / 32, NH / 32), 256>>>(Whm);          // [2048 perm][1536]
    xsplit_kernel<<<(NB * NL * NC / 4) / 256, 256>>>(x);

    // W'^T (perm, fp16) = WhmT_cat @ Wmh_cat^T  (3-term, fp32-accurate)
    gemm_mma<1><<<dim3(NH / 128, NG / 128), 256>>>(pWhmT, pWmhC, 1536, pWp16, nullptr);
    // Wbig^T (perm, fp16) = WhmT_cat @ Wmx_cat^T + Wih^T
    gemm_mma<2><<<dim3(NC / 128, NG / 128), 256>>>(pWhmT, pWmxC, 1536, pWb16, Wih);

    // P = x @ Wbig + bias  (HMMA fp16, Kc=256, fp16 time-major output)
    gemm_mma<0><<<dim3(NG / 128, (NB * NL) / 128), 256>>>(pX16, pWb16, NC, nullptr, nullptr);

    // x_tilde: alpha (time-invariant softmax) then elementwise scale
    alpha_kernel<<<NB, 256>>>(x, Wa, ba);
    scale_kernel<<<(NB * NL * NC / 4) / 256, 256>>>(x, out + (size_t)2 * NB * NL * NH);

    // persistent fused scan (deferred out stores, padded barrier, fp16 P)
    scan_kernel<<<dim3(32, 4), 256, SCAN_SMEM>>>(out);
}

// round 15
// speedup vs baseline: 1.0325x; 1.0325x over previous
#include <cuda_runtime.h>
#include <cuda_bf16.h>
#include <cuda_fp16.h>
#include <math.h>
#include <stdint.h>

#define NB 256   // batch
#define NL 128   // seq len
#define NC 256   // input channels
#define NH 512   // hidden
#define NG 2048  // 4*H

__device__ __forceinline__ uint32_t smem_u32_of(const void* p) {
    uint32_t a;
    asm("{ .reg .u64 t; cvta.to.shared.u64 t, %1; cvt.u32.u64 %0, t; }" : "=r"(a) : "l"(p));
    return a;
}

// ===================== device globals (no allocation allowed) ===============
__device__ float g_bvp[NG];                           // folded bias, permuted cols
__device__ __half g_WhmT_cat[(size_t)NG * 1536];      // [n' perm][1536] = [hi|lo|hi] of Whm^T
__device__ __half g_Wmh_cat[(size_t)NH * 1536];       // [k'][1536] = [hi|hi|lo] of Wmh
__device__ __half g_Wmx_cat[(size_t)NC * 1536];       // [c][1536]  = [hi|hi|lo] of Wmx
__device__ __half g_Wp16[(size_t)NG * NH];            // fp16(W'^T) permuted [n'][512]
__device__ __half g_Wb16[(size_t)NG * NC];            // fp16(Wbig^T) perm [n'][256]
__device__ __half g_x16[(size_t)NB * NL * NC];        // fp16(x) [m][256]
__device__ __half g_h16[2][(size_t)NB * NH];          // hidden fp16, ping-pong
__device__ __half g_P16[(size_t)NL * NB * NG];        // TIME-MAJOR fp16: [t][b][n']
__device__ float g_alpha[NB * NC];                    // softmax weights (time-invariant)
__device__ int   g_bar[4 * 32];                       // barrier counters, 128B apart
// cell state lives in registers inside the persistent scan kernel

// ===================== prep kernels =========================================
__global__ void init_state_kernel() {
    int i = blockIdx.x * blockDim.x + threadIdx.x;
    if (i < NB * NH) g_h16[0][i] = __float2half_rn(0.f);
    if (i < NG) g_bvp[i] = 0.f;
    if (i < 4 * 32) g_bar[i] = 0;
}

__device__ __forceinline__ int perm_col(int n) {       // natural gate col -> permuted
    int j = n & 511, g = n >> 9;
    return ((j >> 3) << 5) | (g << 3) | (j & 7);
}

// split-K bvec: grid (8 n-blocks, 8 k-slices), atomicAdd into zeroed g_bvp
__global__ void bvec_kernel(const float* __restrict__ bih, const float* __restrict__ bhm,
                            const float* __restrict__ bmx, const float* __restrict__ bmh,
                            const float* __restrict__ Whm) {
    int n = blockIdx.x * blockDim.x + threadIdx.x;
    int k0 = blockIdx.y * 64;
    float acc[8] = {};
    for (int kk = 0; kk < 64; kk += 8) {
#pragma unroll
        for (int u = 0; u < 8; u++) {
            int k = k0 + kk + u;
            acc[u] = fmaf(bmx[k] + bmh[k], Whm[(size_t)k * NG + n], acc[u]);
        }
    }
    float s = (blockIdx.y == 0) ? (bih[n] + bhm[n]) : 0.f;
#pragma unroll
    for (int u = 0; u < 8; u++) s += acc[u];
    atomicAdd(&g_bvp[perm_col(n)], s);
}

// elementwise hi/lo split + K-concat: src fp32 [R][512] -> dst fp16 [R][1536]=[hi|hi|lo]
__global__ void splitcat_kernel(const float* __restrict__ src, __half* __restrict__ dst) {
    int i = blockIdx.x * blockDim.x + threadIdx.x;     // float4 index over R*512/4
    float4 v = reinterpret_cast<const float4*>(src)[i];
    float f[4] = {v.x, v.y, v.z, v.w};
    union { __half h[4]; uint2 u; } H, L;
#pragma unroll
    for (int k = 0; k < 4; k++) {
        H.h[k] = __float2half_rn(f[k]);
        L.h[k] = __float2half_rn(f[k] - __half2float(H.h[k]));
    }
    int r = (i * 4) >> 9, m = (i * 4) & 511;
    size_t base = (size_t)r * 1536 + m;
    *reinterpret_cast<uint2*>(dst + base)        = H.u;
    *reinterpret_cast<uint2*>(dst + base + 512)  = H.u;
    *reinterpret_cast<uint2*>(dst + base + 1024) = L.u;
}

// transpose + permute + split: Whm fp32 [512][2048] -> WhmT_cat [2048 perm][1536]=[hi|lo|hi]
__global__ void tsplitT_kernel(const float* __restrict__ src) {
    __shared__ float sA[32][33];
    const int n0 = blockIdx.x * 32, k0 = blockIdx.y * 32;
    const int t = threadIdx.x;
    {
        int nl = t & 31, rr = t >> 5;
#pragma unroll
        for (int it = 0; it < 4; it++) {
            int kl = it * 8 + rr;
            sA[kl][nl] = src[(size_t)(k0 + kl) * NG + n0 + nl];
        }
    }
    __syncthreads();
    int nlo = t >> 3, ks = t & 7;
    int np = perm_col(n0 + nlo);
    union { __half h[4]; uint2 u; } H, L;
#pragma unroll
    for (int kk = 0; kk < 4; kk++) {
        float v = sA[ks * 4 + kk][nlo];
        H.h[kk] = __float2half_rn(v);
        L.h[kk] = __float2half_rn(v - __half2float(H.h[kk]));
    }
    size_t base = (size_t)np * 1536 + k0 + ks * 4;
    *reinterpret_cast<uint2*>(g_WhmT_cat + base)        = H.u;
    *reinterpret_cast<uint2*>(g_WhmT_cat + base + 512)  = L.u;
    *reinterpret_cast<uint2*>(g_WhmT_cat + base + 1024) = H.u;
}

// x fp32 -> fp16 (elementwise)
__global__ void xsplit_kernel(const float* __restrict__ x) {
    size_t i = (size_t)blockIdx.x * blockDim.x + threadIdx.x;  // float4 index
    float4 v = reinterpret_cast<const float4*>(x)[i];
    union { __half h[4]; uint2 u; } H;
    H.h[0] = __float2half_rn(v.x); H.h[1] = __float2half_rn(v.y);
    H.h[2] = __float2half_rn(v.z); H.h[3] = __float2half_rn(v.w);
    reinterpret_cast<uint2*>(g_x16)[i] = H.u;
}

// ===================== shared HMMA GEMM =====================================
// C[M][N] = A[M][Kc] @ Bw[N][Kc]^T  (both K-major fp16).
// EPI=0: += g_bvp, store fp16 to g_P16 (time-major swizzle).
// EPI=1: store fp16 to Wout[r][col], ld=512.
// EPI=2: += Wih[col][inv_perm(r)], store fp16 to Wout[r][col], ld=256.
template <int EPI>
__global__ __launch_bounds__(256)
void gemm_mma(const __half* __restrict__ A, const __half* __restrict__ Bw, int Kc,
              __half* __restrict__ Wout, const float* __restrict__ Wih) {
    constexpr int BM = 128, BN = 128, WN_ = 4, MF = 4;
    __shared__ __half sA[2][BM][40];
    __shared__ __half sB[2][BN][40];
    const int tid = threadIdx.x, lane = tid & 31, w = tid >> 5;
    const int wn0 = (w % WN_) * 32, wm0 = (w / WN_) * 64;
    const int m0 = blockIdx.y * BM, n0 = blockIdx.x * BN;

    auto load_stage = [&](int s, int k0) {
#pragma unroll
        for (int i = 0; i < (BM + BN) * 4 / 256; i++) {
            int q = i * 256 + tid;
            const __half* src;
            uint32_t dst;
            if (q < BM * 4) {
                int r = q >> 2, c = q & 3;
                src = A + (size_t)(m0 + r) * Kc + k0 + c * 8;
                dst = smem_u32_of(&sA[s][r][c * 8]);
            } else {
                int q2 = q - BM * 4, r = q2 >> 2, c = q2 & 3;
                src = Bw + (size_t)(n0 + r) * Kc + k0 + c * 8;
                dst = smem_u32_of(&sB[s][r][c * 8]);
            }
            asm volatile("cp.async.cg.shared.global [%0], [%1], 16;" :: "r"(dst), "l"(src));
        }
        asm volatile("cp.async.commit_group;");
    };

    float acc[MF][4][4] = {};
    const int arow = (lane & 7) + ((lane >> 3) & 1) * 8;
    const int akm  = (lane >> 4) & 1;
    const int brow = lane & 7;
    const int bkm  = (lane >> 3) & 1;

    const int NIT = Kc >> 5;
    load_stage(0, 0);
    for (int it = 0; it < NIT; it++) {
        if (it + 1 < NIT) {
            load_stage((it + 1) & 1, (it + 1) * 32);
            asm volatile("cp.async.wait_group 1;");
        } else {
            asm volatile("cp.async.wait_group 0;");
        }
        __syncthreads();
        int s = it & 1;
#pragma unroll
        for (int ks = 0; ks < 2; ks++) {
            uint32_t aR[MF][4], bR[4][2];
#pragma unroll
            for (int ni = 0; ni < 4; ni++) {
                uint32_t ad = smem_u32_of(&sB[s][wn0 + ni * 8 + brow][ks * 16 + bkm * 8]);
                asm volatile("ldmatrix.sync.aligned.m8n8.x2.shared.b16 {%0,%1}, [%2];"
                             : "=r"(bR[ni][0]), "=r"(bR[ni][1]) : "r"(ad));
            }
#pragma unroll
            for (int mi = 0; mi < MF; mi++) {
                uint32_t ad = smem_u32_of(&sA[s][wm0 + mi * 16 + arow][ks * 16 + akm * 8]);
                asm volatile("ldmatrix.sync.aligned.m8n8.x4.shared.b16 {%0,%1,%2,%3}, [%4];"
                             : "=r"(aR[mi][0]), "=r"(aR[mi][1]), "=r"(aR[mi][2]), "=r"(aR[mi][3])
                             : "r"(ad));
            }
#pragma unroll
            for (int mi = 0; mi < MF; mi++)
#pragma unroll
                for (int ni = 0; ni < 4; ni++)
                    asm volatile(
                        "mma.sync.aligned.m16n8k16.row.col.f32.f16.f16.f32 "
                        "{%0,%1,%2,%3}, {%4,%5,%6,%7}, {%8,%9}, {%0,%1,%2,%3};"
                        : "+f"(acc[mi][ni][0]), "+f"(acc[mi][ni][1]),
                          "+f"(acc[mi][ni][2]), "+f"(acc[mi][ni][3])
                        : "r"(aR[mi][0]), "r"(aR[mi][1]), "r"(aR[mi][2]), "r"(aR[mi][3]),
                          "r"(bR[ni][0]), "r"(bR[ni][1]));
        }
        __syncthreads();
    }

    constexpr int Nld = (EPI == 1) ? NH : NC;
#pragma unroll
    for (int mi = 0; mi < MF; mi++) {
#pragma unroll
        for (int half = 0; half < 2; half++) {
            int r = m0 + wm0 + mi * 16 + (lane >> 2) + half * 8;
            if (EPI == 0) {
                size_t dr = (size_t)(r & (NL - 1)) * NB + (size_t)(r >> 7);
#pragma unroll
                for (int ni = 0; ni < 4; ni++) {
                    int col = n0 + wn0 + ni * 8 + (lane & 3) * 2;
                    *reinterpret_cast<__half2*>(&g_P16[dr * NG + col]) =
                        __floats2half2_rn(acc[mi][ni][half * 2 + 0] + g_bvp[col],
                                          acc[mi][ni][half * 2 + 1] + g_bvp[col + 1]);
                }
            } else {
                int n_nat = 0;
                if (EPI == 2) {
                    int low3 = r & 7, g = (r >> 3) & 3, jj = ((r >> 5) << 3) | low3;
                    n_nat = (g << 9) | jj;
                }
#pragma unroll
                for (int ni = 0; ni < 4; ni++) {
                    int col = n0 + wn0 + ni * 8 + (lane & 3) * 2;
                    float v0 = acc[mi][ni][half * 2 + 0];
                    float v1 = acc[mi][ni][half * 2 + 1];
                    if (EPI == 2) {
                        v0 += Wih[(size_t)col * NG + n_nat];
                        v1 += Wih[(size_t)(col + 1) * NG + n_nat];
                    }
                    *reinterpret_cast<__half2*>(Wout + (size_t)r * Nld + col) =
                        __halves2half2(__float2half_rn(v0), __float2half_rn(v1));
                }
            }
        }
    }
}

// ===================== x_tilde: alpha + scale ================================
__global__ void alpha_kernel(const float* __restrict__ x, const float* __restrict__ Wa,
                             const float* __restrict__ ba) {
    __shared__ float red[NC];
    __shared__ float s_wa[NL];
    int b = blockIdx.x, c = threadIdx.x;
    if (c < NL) s_wa[c] = Wa[2 * NH + c];
    __syncthreads();
    const float* xb = x + (size_t)b * NL * NC;
    float s = ba[0];
#pragma unroll 16
    for (int l = 0; l < NL; l++) s = fmaf(xb[(size_t)l * NC + c], s_wa[l], s);
    red[c] = s; __syncthreads();
    for (int o = NC / 2; o > 0; o >>= 1) { if (c < o) red[c] = fmaxf(red[c], red[c + o]); __syncthreads(); }
    float mx = red[0]; __syncthreads();
    float e = expf(s - mx);
    red[c] = e; __syncthreads();
    for (int o = NC / 2; o > 0; o >>= 1) { if (c < o) red[c] += red[c + o]; __syncthreads(); }
    g_alpha[b * NC + c] = e / red[0];
}

__global__ void scale_kernel(const float* __restrict__ x, float* __restrict__ out) {
    size_t i = (size_t)blockIdx.x * blockDim.x + threadIdx.x;  // float4 index
    float4 v = reinterpret_cast<const float4*>(x)[i];
    int b = (int)(i >> 13);                    // / (NL*NC/4)
    int c4 = (int)(i & 63) << 2;
    float4 a = *reinterpret_cast<const float4*>(g_alpha + b * NC + c4);
    v.x *= a.x; v.y *= a.y; v.z *= a.z; v.w *= a.w;
    reinterpret_cast<float4*>(out)[i] = v;
}

// ===================== persistent scan kernel ===============================
// R13/R10 ordering: compute -> ALL stores + loadP(t+1) -> fence -> barrier.
static constexpr int SBP = 520;                        // halves (1040 B pitch)
static constexpr int SAP = 136;                        // halves (272 B pitch)
static constexpr int SA_STAGE = 64 * SAP;
static constexpr int SCAN_SMEM = (64 * SBP + 4 * SA_STAGE) * 2;   // 136,192 B

__device__ __forceinline__ void wait_grp(int n) {
    switch (n) {
        case 0: asm volatile("cp.async.wait_group 0;" ::: "memory"); break;
        case 1: asm volatile("cp.async.wait_group 1;" ::: "memory"); break;
        case 2: asm volatile("cp.async.wait_group 2;" ::: "memory"); break;
        default: asm volatile("cp.async.wait_group 3;" ::: "memory"); break;
    }
}

__global__ __launch_bounds__(256)
void scan_kernel(float* __restrict__ out) {
    extern __shared__ __half sm16[];
    __half* sB = sm16;                                // [64][520]
    __half* sA = sm16 + 64 * SBP;                     // [4][64][136]
    const int tid = threadIdx.x, lane = tid & 31, w = tid >> 5;
    const int n0 = blockIdx.x * 64, m0 = blockIdx.y * 64, grp = blockIdx.y;
    const int wn0 = (w & 1) * 32, wm0 = (w >> 1) * 16;

    // ---- resident B tile: W1 rows n0..n0+63, 512 cols ----------------------
#pragma unroll
    for (int i = 0; i < 16; i++) {
        int q = i * 256 + tid;
        int r = q >> 6, cc = q & 63;
        asm volatile("cp.async.cg.shared.global [%0], [%1], 16;"
                     :: "r"(smem_u32_of(sB + r * SBP + cc * 8)),
                        "l"(g_Wp16 + (size_t)(n0 + r) * NH + cc * 8));
    }
    asm volatile("cp.async.commit_group;");
    asm volatile("cp.async.wait_group 0;");
    __syncthreads();

    const int arow = (lane & 7) + ((lane >> 3) & 1) * 8;
    const int akm  = (lane >> 4) & 1;
    const int browB = ((lane >> 4) & 1) * 8 + (lane & 7);
    const int bkmB  = (lane >> 3) & 1;
    const int p0 = (lane & 3) * 2;
    const int j = ((n0 + wn0) >> 5) * 8 + p0;         // hidden unit (even)

    float creg[2][2] = {};                            // cell state in registers
    uint32_t pv[2][4];                                // prefetched P (half2 bits)

    auto loadP = [&](int tt) {
        const __half* Pt = g_P16 + (size_t)tt * NB * NG;
#pragma unroll
        for (int half = 0; half < 2; half++) {
            int b = m0 + wm0 + (lane >> 2) + half * 8;
#pragma unroll
            for (int ni = 0; ni < 4; ni++)
                pv[half][ni] = __ldg(reinterpret_cast<const uint32_t*>(
                    Pt + (size_t)b * NG + n0 + wn0 + ni * 8 + p0));
        }
    };
    loadP(0);

    for (int t = 0; t < NL; t++) {
        const int par = t & 1;
        const __half* hsrc = g_h16[par];

        // issue ALL 4 A chunks (16 KB each) immediately
#pragma unroll
        for (int c = 0; c < 4; c++) {
#pragma unroll
            for (int i = 0; i < 4; i++) {
                int q = i * 256 + tid;
                int r = q >> 4, cc = q & 15;
                asm volatile("cp.async.cg.shared.global [%0], [%1], 16;"
                             :: "r"(smem_u32_of(sA + c * SA_STAGE + r * SAP + cc * 8)),
                                "l"(hsrc + (size_t)(m0 + r) * NH + c * 128 + cc * 8));
            }
            asm volatile("cp.async.commit_group;");
        }

        float acc[4][4] = {};
#pragma unroll
        for (int c = 0; c < 4; c++) {
            wait_grp(3 - c);
            __syncthreads();
            const __half* As = sA + c * SA_STAGE;
            const int kb = c * 128;
#pragma unroll
            for (int ks = 0; ks < 8; ks++) {
                uint32_t aR[4];
                asm volatile("ldmatrix.sync.aligned.m8n8.x4.shared.b16 {%0,%1,%2,%3}, [%4];"
                             : "=r"(aR[0]), "=r"(aR[1]), "=r"(aR[2]), "=r"(aR[3])
                             : "r"(smem_u32_of(As + (wm0 + arow) * SAP + ks * 16 + akm * 8)));
#pragma unroll
                for (int p = 0; p < 2; p++) {
                    uint32_t b4[4];
                    asm volatile("ldmatrix.sync.aligned.m8n8.x4.shared.b16 {%0,%1,%2,%3}, [%4];"
                                 : "=r"(b4[0]), "=r"(b4[1]), "=r"(b4[2]), "=r"(b4[3])
                                 : "r"(smem_u32_of(sB + (wn0 + p * 16 + browB) * SBP
                                                   + kb + ks * 16 + bkmB * 8)));
                    asm volatile(
                        "mma.sync.aligned.m16n8k16.row.col.f32.f16.f16.f32 "
                        "{%0,%1,%2,%3}, {%4,%5,%6,%7}, {%8,%9}, {%0,%1,%2,%3};"
                        : "+f"(acc[2 * p][0]), "+f"(acc[2 * p][1]),
                          "+f"(acc[2 * p][2]), "+f"(acc[2 * p][3])
                        : "r"(aR[0]), "r"(aR[1]), "r"(aR[2]), "r"(aR[3]),
                          "r"(b4[0]), "r"(b4[1]));
                    asm volatile(
                        "mma.sync.aligned.m16n8k16.row.col.f32.f16.f16.f32 "
                        "{%0,%1,%2,%3}, {%4,%5,%6,%7}, {%8,%9}, {%0,%1,%2,%3};"
                        : "+f"(acc[2 * p + 1][0]), "+f"(acc[2 * p + 1][1]),
                          "+f"(acc[2 * p + 1][2]), "+f"(acc[2 * p + 1][3])
                        : "r"(aR[0]), "r"(aR[1]), "r"(aR[2]), "r"(aR[3]),
                          "r"(b4[2]), "r"(b4[3]));
                }
            }
        }

        // ---- fused LSTM pointwise epilogue (cell state in registers) -------
        __half* hdst = g_h16[par ^ 1];
#pragma unroll
        for (int half = 0; half < 2; half++) {
            int b = m0 + wm0 + (lane >> 2) + half * 8;
            float hn[2], cn[2];
            float2 pf0 = __half22float2(*reinterpret_cast<__half2*>(&pv[half][0]));
            float2 pf1 = __half22float2(*reinterpret_cast<__half2*>(&pv[half][1]));
            float2 pf2 = __half22float2(*reinterpret_cast<__half2*>(&pv[half][2]));
            float2 pf3 = __half22float2(*reinterpret_cast<__half2*>(&pv[half][3]));
#pragma unroll
            for (int e = 0; e < 2; e++) {
                int a = half * 2 + e;
                float iv = acc[0][a] + (e ? pf0.y : pf0.x);
                float fv = acc[1][a] + (e ? pf1.y : pf1.x);
                float gv = acc[2][a] + (e ? pf2.y : pf2.x);
                float ov = acc[3][a] + (e ? pf3.y : pf3.x);
                float si = 1.f / (1.f + expf(-iv));
                float sf = 1.f / (1.f + expf(-fv));
                float so = 1.f / (1.f + expf(-ov));
                float tg = tanhf(gv);
                float Cn = sf * creg[half][e] + si * tg;
                creg[half][e] = Cn;
                cn[e] = Cn;
                hn[e] = so * tanhf(Cn);
            }
            size_t o = (size_t)b * (NL * NH) + (size_t)t * NH + j;
            *reinterpret_cast<float2*>(&out[o]) = make_float2(hn[0], hn[1]);
            *reinterpret_cast<float2*>(&out[o + (size_t)NB * NL * NH]) = make_float2(cn[0], cn[1]);
            *reinterpret_cast<__half2*>(hdst + (size_t)b * NH + j) =
                __halves2half2(__float2half_rn(hn[0]), __float2half_rn(hn[1]));
        }

        // prefetch P for next step — overlaps fence + barrier wait
        if (t + 1 < NL) loadP(t + 1);

        // ---- per-m-group barrier (padded counters) ------------------------
        __threadfence();
        __syncthreads();
        if (tid == 0) {
            atomicAdd(&g_bar[grp * 32], 1);
            int target = 32 * (t + 1);
            while (*((volatile int*)&g_bar[grp * 32]) < target) __nanosleep(32);
        }
        __syncthreads();
    }
}

// ===================== host =================================================
extern "C" void kernel_launch(void* const* d_in, const int* in_sizes, int n_in,
                              void* d_out, int out_size) {
    const float* x   = (const float*)d_in[0];
    const float* Wih = (const float*)d_in[1];
    const float* bih = (const float*)d_in[2];
    const float* Wmx = (const float*)d_in[3];
    const float* bmx = (const float*)d_in[4];
    const float* Wmh = (const float*)d_in[5];
    const float* bmh = (const float*)d_in[6];
    const float* Whm = (const float*)d_in[7];
    const float* bhm = (const float*)d_in[8];
    const float* Wa  = (const float*)d_in[9];
    const float* ba  = (const float*)d_in[10];
    float* out = (float*)d_out;

    __half *pWhmT, *pWmhC, *pWmxC, *pWp16, *pWb16, *pX16;
    cudaGetSymbolAddress((void**)&pWhmT, g_WhmT_cat);
    cudaGetSymbolAddress((void**)&pWmhC, g_Wmh_cat);
    cudaGetSymbolAddress((void**)&pWmxC, g_Wmx_cat);
    cudaGetSymbolAddress((void**)&pWp16, g_Wp16);
    cudaGetSymbolAddress((void**)&pWb16, g_Wb16);
    cudaGetSymbolAddress((void**)&pX16,  g_x16);

    cudaFuncSetAttribute(scan_kernel, cudaFuncAttributeMaxDynamicSharedMemorySize, SCAN_SMEM);

    init_state_kernel<<<(NB * NH + 255) / 256, 256>>>();
    bvec_kernel<<<dim3(8, 8), 256>>>(bih, bhm, bmx, bmh, Whm);

    // operand prep for HMMA weight folding
    splitcat_kernel<<<(NH * NH / 4) / 256, 256>>>(Wmh, pWmhC);     // [512][1536]
    splitcat_kernel<<<(NC * NH / 4) / 256, 256>>>(Wmx, pWmxC);     // [256][1536]
    tsplitT_kernel<<<dim3(NG / 32, NH / 32), 256>>>(Whm);          // [2048 perm][1536]
    xsplit_kernel<<<(NB * NL * NC / 4) / 256, 256>>>(x);

    // W'^T (perm, fp16) = WhmT_cat @ Wmh_cat^T  (3-term, fp32-accurate)
    gemm_mma<1><<<dim3(NH / 128, NG / 128), 256>>>(pWhmT, pWmhC, 1536, pWp16, nullptr);
    // Wbig^T (perm, fp16) = WhmT_cat @ Wmx_cat^T + Wih^T
    gemm_mma<2><<<dim3(NC / 128, NG / 128), 256>>>(pWhmT, pWmxC, 1536, pWb16, Wih);

    // P = x @ Wbig + bias  (HMMA fp16, Kc=256, fp16 time-major output)
    gemm_mma<0><<<dim3(NG / 128, (NB * NL) / 128), 256>>>(pX16, pWb16, NC, nullptr, nullptr);

    // x_tilde: alpha (time-invariant softmax) then elementwise scale
    alpha_kernel<<<NB, 256>>>(x, Wa, ba);
    scale_kernel<<<(NB * NL * NC / 4) / 256, 256>>>(x, out + (size_t)2 * NB * NL * NH);

    // persistent fused scan (R13 ordering + padded barrier + fp16 P)
    scan_kernel<<<dim3(32, 4), 256, SCAN_SMEM>>>(out);
}